// round 14
// baseline (speedup 1.0000x reference)
#include <cuda_runtime.h>
#include <cstdint>
#include <math.h>

#define N_  32
#define T_  1024
#define D_  512
#define H_  512
#define G4  2048

#define NB   128
#define NTH  576    // 16 GEMM warps + 2 reduce warps
#define APW  288    // partial plane stride (ull): 4 np * 72

typedef unsigned long long ull;

__device__ __forceinline__ void fma2(ull& d, const ull a, const ull b) {
    asm("fma.rn.f32x2 %0, %1, %2, %0;" : "+l"(d) : "l"(a), "l"(b));
}
__device__ __forceinline__ void add2(ull& d, const ull a) {
    asm("add.rn.f32x2 %0, %0, %1;" : "+l"(d) : "l"(a));
}
__device__ __forceinline__ ull bcast2(float x) {
    ull r; asm("mov.b64 %0, {%1, %1};" : "=l"(r) : "f"(x)); return r;
}
__device__ __forceinline__ void unpack2(float& lo, float& hi, ull a) {
    asm("mov.b64 {%0, %1}, %2;" : "=f"(lo), "=f"(hi) : "l"(a));
}
__device__ __forceinline__ float fsig(float x) { return 1.f / (1.f + __expf(-x)); }
__device__ __forceinline__ float ftanh(float x) { return 2.f / (1.f + __expf(-2.f * x)) - 1.f; }

// ---- cp.async helpers ----
__device__ __forceinline__ void cp_async16(void* dst, const void* src) {
    unsigned s = (unsigned)__cvta_generic_to_shared(dst);
    asm volatile("cp.async.cg.shared.global [%0], [%1], 16;" :: "r"(s), "l"(src));
}
__device__ __forceinline__ void cp_commit() {
    asm volatile("cp.async.commit_group;" ::: "memory");
}
template <int NN> __device__ __forceinline__ void cp_wait() {
    asm volatile("cp.async.wait_group %0;" :: "n"(NN) : "memory");
}

// ---- tf32 mma helpers ----
__device__ __forceinline__ uint32_t f2tf(float x) {
    uint32_t r; asm("cvt.rna.tf32.f32 %0, %1;" : "=r"(r) : "f"(x)); return r;
}
__device__ __forceinline__ void mma_tf32(float* c, const uint32_t* a, const uint32_t* b) {
    asm("mma.sync.aligned.m16n8k8.row.col.f32.tf32.tf32.f32 "
        "{%0,%1,%2,%3},{%4,%5,%6,%7},{%8,%9},{%0,%1,%2,%3};"
        : "+f"(c[0]), "+f"(c[1]), "+f"(c[2]), "+f"(c[3])
        : "r"(a[0]), "r"(a[1]), "r"(a[2]), "r"(a[3]), "r"(b[0]), "r"(b[1]));
}

// ---------------- device scratch -------------------------------------------------
__device__ float g_xw [(size_t)N_ * T_ * G4];          // phase1 out: [n][t][2048]
__device__ float g_xw2[(size_t)T_ * NB * 512];         // [t][cta][n8][gate][j16]
__device__ float g_hT [(size_t)(T_ + 1) * 4 * 4096];   // h history: [t][g][k(512)][n8(8)]
__device__ unsigned int g_f[4][32];                    // flag[g][r] = v: h(v-1) published

// ---------------- init: flags=1 + h0 -> g_hT[0] ------------------------------------
__global__ void init_state_kernel(const float* __restrict__ h0)
{
    int i = blockIdx.x * blockDim.x + threadIdx.x;
    if (i < 128) g_f[i >> 5][i & 31] = 1u;
    if (i < 4 * 512 * 8) {
        int g = i >> 12, k = (i >> 3) & 511, n8 = i & 7;
        g_hT[(size_t)g * 4096 + k * 8 + n8] = h0[(size_t)(g * 8 + n8) * H_ + k];
    }
}

// ---------------- Phase 1: xw = x @ Wx + b  via tf32 tensor cores ------------------
#define AS_STR 40
#define BS_STR 132
#define AS_BUF (128 * AS_STR)
#define BS_BUF (32 * BS_STR)

__global__ __launch_bounds__(256) void gemm_xw_tc(const float* __restrict__ x,
                                                  const float* __restrict__ Wx,
                                                  const float* __restrict__ bias)
{
    extern __shared__ float sm1[];
    float* As = sm1;
    float* Bs = sm1 + 2 * AS_BUF;

    const int tid  = threadIdx.x;
    const int bn   = blockIdx.x, bm = blockIdx.y;
    const int warp = tid >> 5, lane = tid & 31;
    const int wy = warp & 1, wx = warp >> 1;
    const int g  = lane >> 2, tg = lane & 3;

    float acc[4][4][4];
#pragma unroll
    for (int mi = 0; mi < 4; mi++)
#pragma unroll
        for (int ni = 0; ni < 4; ni++)
#pragma unroll
            for (int c = 0; c < 4; c++) acc[mi][ni][c] = 0.f;

    {
#pragma unroll
        for (int i = 0; i < 4; i++) {
            int flat = i * 256 + tid;
            int m = flat >> 3, kc = flat & 7;
            cp_async16(As + m * AS_STR + kc * 4,
                       x + (size_t)(bm * 128 + m) * D_ + kc * 4);
        }
#pragma unroll
        for (int i = 0; i < 4; i++) {
            int flat = i * 256 + tid;
            int k = flat >> 5, nc = flat & 31;
            cp_async16(Bs + k * BS_STR + nc * 4,
                       Wx + (size_t)k * G4 + bn * 128 + nc * 4);
        }
        cp_commit();
    }

    for (int it = 0; it < 16; it++) {
        if (it < 15) {
            const int k0 = (it + 1) * 32;
            const int nb = (it + 1) & 1;
#pragma unroll
            for (int i = 0; i < 4; i++) {
                int flat = i * 256 + tid;
                int m = flat >> 3, kc = flat & 7;
                cp_async16(As + nb * AS_BUF + m * AS_STR + kc * 4,
                           x + (size_t)(bm * 128 + m) * D_ + k0 + kc * 4);
            }
#pragma unroll
            for (int i = 0; i < 4; i++) {
                int flat = i * 256 + tid;
                int k = flat >> 5, nc = flat & 31;
                cp_async16(Bs + nb * BS_BUF + k * BS_STR + nc * 4,
                           Wx + (size_t)(k0 + k) * G4 + bn * 128 + nc * 4);
            }
            cp_commit();
            cp_wait<1>();
        } else {
            cp_wait<0>();
        }
        __syncthreads();

        const float* Ab = As + (it & 1) * AS_BUF;
        const float* Bb = Bs + (it & 1) * BS_BUF;
#pragma unroll
        for (int ks = 0; ks < 4; ks++) {
            uint32_t af[4][4], bf[4][2];
#pragma unroll
            for (int mi = 0; mi < 4; mi++) {
                const float* ap_ = Ab + (wy * 64 + mi * 16) * AS_STR + ks * 8;
                af[mi][0] = f2tf(ap_[ g      * AS_STR + tg    ]);
                af[mi][1] = f2tf(ap_[(g + 8) * AS_STR + tg    ]);
                af[mi][2] = f2tf(ap_[ g      * AS_STR + tg + 4]);
                af[mi][3] = f2tf(ap_[(g + 8) * AS_STR + tg + 4]);
            }
#pragma unroll
            for (int ni = 0; ni < 4; ni++) {
                const float* bp_ = Bb + ks * 8 * BS_STR + wx * 32 + ni * 8 + g;
                bf[ni][0] = f2tf(bp_[ tg      * BS_STR]);
                bf[ni][1] = f2tf(bp_[(tg + 4) * BS_STR]);
            }
#pragma unroll
            for (int mi = 0; mi < 4; mi++)
#pragma unroll
                for (int ni = 0; ni < 4; ni++)
                    mma_tf32(acc[mi][ni], af[mi], bf[ni]);
        }
        __syncthreads();
    }

#pragma unroll
    for (int ni = 0; ni < 4; ni++) {
        int col = bn * 128 + wx * 32 + ni * 8 + 2 * tg;
        float b0 = bias[col], b1 = bias[col + 1];
#pragma unroll
        for (int mi = 0; mi < 4; mi++) {
            int row0 = bm * 128 + wy * 64 + mi * 16 + g;
            float2 v0; v0.x = acc[mi][ni][0] + b0; v0.y = acc[mi][ni][1] + b1;
            float2 v1; v1.x = acc[mi][ni][2] + b0; v1.y = acc[mi][ni][3] + b1;
            *(float2*)(g_xw + (size_t)row0 * G4 + col)       = v0;
            *(float2*)(g_xw + (size_t)(row0 + 8) * G4 + col) = v1;
        }
    }
}

// ---------------- T1: g_xw[n][t][2048] -> g_xw2[t][cta][n8][gate][j16] -------------
__global__ __launch_bounds__(512) void xw_transpose_kernel()
{
    const int t = blockIdx.x;
    const int g = blockIdx.y;
#pragma unroll
    for (int it = 0; it < 8; it++) {
        int flat = it * 512 + threadIdx.x;
        int r    = flat >> 7;
        int n8   = (flat >> 4) & 7;
        int gate = (flat >> 2) & 3;
        int jl4  = flat & 3;
        float4 v = __ldcg((const float4*)(g_xw +
                    ((size_t)(g * 8 + n8) * T_ + t) * G4 + gate * 512 + r * 16 + jl4 * 4));
        *(float4*)(g_xw2 + (((size_t)t * NB + g * 32 + r) * 8 + n8) * 64
                         + gate * 16 + jl4 * 4) = v;
    }
}

// ---------------- Phase 2: per-group persistent, per-rank flag dataflow ------------
extern __shared__ float smem_dyn[];

__global__ __launch_bounds__(NTH, 1) void lstm_rec_kernel(const float* __restrict__ Wh)
{
    float* ws = smem_dyn;                       // [512][64]  (128KB)
    float* hs = ws + 512 * 64;                  // [512][8]   (16KB)
    ull*   ap = (ull*)(hs + 512 * 8);           // [2][16][APW] (72KB)

    const int b   = blockIdx.x;
    const int g   = b >> 5;          // group 0..3 (batch n = g*8..g*8+7)
    const int r   = b & 31;          // rank: j-columns [r*16, r*16+16)
    const int tid = threadIdx.x;

    for (int idx = tid; idx < 512 * 64; idx += NTH) {
        int k = idx >> 6, c = idx & 63;
        ws[idx] = Wh[(size_t)k * G4 + (c >> 4) * 512 + r * 16 + (c & 15)];
    }
    __syncthreads();

    if (tid < 512) {
        // ================= GEMM worker warps =================
        const int w    = tid >> 5;
        const int lane = tid & 31;
        const int kg   = lane >> 4;
        const int pos  = lane & 15;
        const int cg4  = pos * 4;
        const int kbase = w * 32 + kg * 16;
        const ull* fp = (const ull*)&g_f[g][2 * w];   // flags of my 2 producers

        for (int t = 0; t < T_; t++) {
            // wait for MY two producers only (8B acquire load, all lanes same addr)
            {
                unsigned target = (unsigned)t + 1u;
                while (true) {
                    ull v;
                    asm volatile("ld.acquire.gpu.global.b64 %0, [%1];"
                                 : "=l"(v) : "l"(fp) : "memory");
                    if ((unsigned)v >= target && (unsigned)(v >> 32) >= target) break;
                }
            }
            // stage own k-slice of h (two float4 per lane)
            const float* hb = g_hT + ((size_t)t * 4 + g) * 4096;
            {
                int off = (w * 32 + (lane >> 1)) * 8 + (lane & 1) * 4;
                float4 v0 = __ldcg((const float4*)(hb + off));
                float4 v1 = __ldcg((const float4*)(hb + off + 128));
                *(float4*)(hs + off) = v0;
                *(float4*)(hs + off + 128) = v1;
            }
            __syncwarp();

            ull acc[4][4];
#pragma unroll
            for (int u = 0; u < 4; u++)
#pragma unroll
                for (int c = 0; c < 4; c++) acc[u][c] = 0ULL;

#pragma unroll
            for (int i = 0; i < 16; i++) {
                int k = kbase + i;
                ulonglong2 hA = *(const ulonglong2*)(hs + k * 8);
                ulonglong2 hB = *(const ulonglong2*)(hs + k * 8 + 4);
                ull hv[4] = {hA.x, hA.y, hB.x, hB.y};
                float4 wf = *(const float4*)(ws + k * 64 + cg4);
                ull wb[4] = {bcast2(wf.x), bcast2(wf.y), bcast2(wf.z), bcast2(wf.w)};
#pragma unroll
                for (int u = 0; u < 4; u++)
#pragma unroll
                    for (int c = 0; c < 4; c++)
                        fma2(acc[u][c], hv[u], wb[c]);
            }
#pragma unroll
            for (int u = 0; u < 4; u++)
#pragma unroll
                for (int c = 0; c < 4; c++) {
                    ull o = __shfl_xor_sync(0xFFFFFFFFu, acc[u][c], 16);
                    add2(acc[u][c], o);
                }
            if (kg == 0) {
                ull* pl = ap + (t & 1) * (16 * APW) + w * APW;
#pragma unroll
                for (int u = 0; u < 4; u++) {
                    ulonglong2 s0, s1;
                    s0.x = acc[u][0]; s0.y = acc[u][1];
                    s1.x = acc[u][2]; s1.y = acc[u][3];
                    *(ulonglong2*)(pl + u * 72 + cg4)     = s0;
                    *(ulonglong2*)(pl + u * 72 + cg4 + 2) = s1;
                }
            }
            // phase-alternating rendezvous with reduce warps (bar.sync drains STS)
            asm volatile("bar.sync %0, %1;" :: "r"(1 + (t & 1)), "n"(NTH) : "memory");
        }
    } else {
        // ================= reduce / gates warps (tid 512..575) =================
        const int rt = tid - 512;
        const int np = rt >> 4, jc = rt & 15;

        float c0v = 0.f, c1v = 0.f;
        float xwr[2][4];
        {
            const float* xb = g_xw2 + (size_t)b * 512;
#pragma unroll
            for (int rr = 0; rr < 2; rr++)
#pragma unroll
                for (int q = 0; q < 4; q++)
                    xwr[rr][q] = __ldcg(xb + (2 * np + rr) * 64 + q * 16 + jc);
        }

        for (int t = 0; t < T_; t++) {
            asm volatile("bar.sync %0, %1;" :: "r"(1 + (t & 1)), "n"(NTH) : "memory");

            ull s0 = 0ULL, s1 = 0ULL, s2 = 0ULL, s3 = 0ULL;
            const ull* base = ap + (t & 1) * (16 * APW) + np * 72 + jc;
#pragma unroll
            for (int p = 0; p < 16; p++) {
                const ull* pl = base + p * APW;
                add2(s0, pl[0]);
                add2(s1, pl[16]);
                add2(s2, pl[32]);
                add2(s3, pl[48]);
            }
            float a0l, a0h, a1l, a1h, a2l, a2h, a3l, a3h;
            unpack2(a0l, a0h, s0);
            unpack2(a1l, a1h, s1);
            unpack2(a2l, a2h, s2);
            unpack2(a3l, a3h, s3);

            float ig0 = fsig(a0l + xwr[0][0]);
            float fg0 = fsig(a1l + xwr[0][1]);
            float og0 = fsig(a2l + xwr[0][2]);
            float gg0 = ftanh(a3l + xwr[0][3]);
            c0v = fg0 * c0v + ig0 * gg0;
            float hn0 = og0 * ftanh(c0v);

            float ig1 = fsig(a0h + xwr[1][0]);
            float fg1 = fsig(a1h + xwr[1][1]);
            float og1 = fsig(a2h + xwr[1][2]);
            float gg1 = ftanh(a3h + xwr[1][3]);
            c1v = fg1 * c1v + ig1 * gg1;
            float hn1 = og1 * ftanh(c1v);

            // publish h(t+1) to L2
            {
                float* dst = g_hT + ((size_t)(t + 1) * 4 + g) * 4096 + (r * 16 + jc) * 8 + 2 * np;
                asm volatile("st.global.cg.v2.f32 [%0], {%1, %2};"
                             :: "l"(dst), "f"(hn0), "f"(hn1) : "memory");
            }
            asm volatile("bar.sync 3, 64;" ::: "memory");
            if (rt == 0) {
                __threadfence();
                unsigned nf = (unsigned)t + 2u;
                asm volatile("st.release.gpu.global.u32 [%0], %1;"
                             :: "l"(&g_f[g][r]), "r"(nf) : "memory");
            }
            // off critical path: next xw prefetch
            if (t + 1 < T_) {
                const float* xb = g_xw2 + ((size_t)(t + 1) * NB + b) * 512;
#pragma unroll
                for (int rr = 0; rr < 2; rr++)
#pragma unroll
                    for (int q = 0; q < 4; q++)
                        xwr[rr][q] = __ldcg(xb + (2 * np + rr) * 64 + q * 16 + jc);
            }
        }
    }
}

// ---------------- T2: g_hT[t+1][g][j][n8] -> out[n][t][j] --------------------------
__global__ __launch_bounds__(512) void out_transpose_kernel(float* __restrict__ out)
{
    extern __shared__ float sm[];
    const int t = blockIdx.x;
    const int tid = threadIdx.x;
    const float* src = g_hT + (size_t)(t + 1) * 4 * 4096;
#pragma unroll
    for (int it = 0; it < 8; it++) {
        int idx = tid + it * 512;
        *(float4*)(sm + idx * 4) = __ldcg((const float4*)(src + idx * 4));
    }
    __syncthreads();
    const int n = tid >> 4, jb = (tid & 15) * 32;
    const int gbase = (n >> 3) * 4096, n8 = n & 7;
#pragma unroll
    for (int it = 0; it < 8; it++) {
        int j = jb + it * 4;
        float4 v;
        v.x = sm[gbase + (j + 0) * 8 + n8];
        v.y = sm[gbase + (j + 1) * 8 + n8];
        v.z = sm[gbase + (j + 2) * 8 + n8];
        v.w = sm[gbase + (j + 3) * 8 + n8];
        *(float4*)(out + ((size_t)n * T_ + t) * H_ + j) = v;
    }
}

// ---------------- launch ----------------------------------------------------------
extern "C" void kernel_launch(void* const* d_in, const int* in_sizes, int n_in,
                              void* d_out, int out_size)
{
    const float* x    = (const float*)d_in[0];
    const float* h0   = (const float*)d_in[1];
    const float* Wx   = (const float*)d_in[2];
    const float* Wh   = (const float*)d_in[3];
    const float* bias = (const float*)d_in[4];
    float* out = (float*)d_out;

    init_state_kernel<<<64, 256>>>(h0);

    const int sh1 = (2 * AS_BUF + 2 * BS_BUF) * (int)sizeof(float);
    cudaFuncSetAttribute(gemm_xw_tc, cudaFuncAttributeMaxDynamicSharedMemorySize, sh1);
    dim3 g1(G4 / 128, (N_ * T_) / 128);
    gemm_xw_tc<<<g1, 256, sh1>>>(x, Wx, bias);

    dim3 gt1(T_, 4);
    xw_transpose_kernel<<<gt1, 512>>>();

    const int shmem = (512 * 64 + 512 * 8) * 4 + 2 * 16 * APW * 8;
    cudaFuncSetAttribute(lstm_rec_kernel, cudaFuncAttributeMaxDynamicSharedMemorySize, shmem);
    lstm_rec_kernel<<<NB, NTH, shmem>>>(Wh);

    cudaFuncSetAttribute(out_transpose_kernel, cudaFuncAttributeMaxDynamicSharedMemorySize, 65536);
    out_transpose_kernel<<<T_, 512, 65536>>>(out);
}

// round 15
// speedup vs baseline: 3.4369x; 3.4369x over previous
#include <cuda_runtime.h>
#include <cstdint>
#include <math.h>

#define N_  32
#define T_  1024
#define D_  512
#define H_  512
#define G4  2048

#define NB   128
#define NTH  576    // 16 GEMM warps + 2 reduce warps
#define APW  288    // partial plane stride (ull): 4 np * 72

typedef unsigned long long ull;

__device__ __forceinline__ void fma2(ull& d, const ull a, const ull b) {
    asm("fma.rn.f32x2 %0, %1, %2, %0;" : "+l"(d) : "l"(a), "l"(b));
}
__device__ __forceinline__ void add2(ull& d, const ull a) {
    asm("add.rn.f32x2 %0, %0, %1;" : "+l"(d) : "l"(a));
}
__device__ __forceinline__ ull bcast2(float x) {
    ull r; asm("mov.b64 %0, {%1, %1};" : "=l"(r) : "f"(x)); return r;
}
__device__ __forceinline__ void unpack2(float& lo, float& hi, ull a) {
    asm("mov.b64 {%0, %1}, %2;" : "=f"(lo), "=f"(hi) : "l"(a));
}
__device__ __forceinline__ float fsig(float x) { return 1.f / (1.f + __expf(-x)); }
__device__ __forceinline__ float ftanh(float x) { return 2.f / (1.f + __expf(-2.f * x)) - 1.f; }

// ---- cp.async helpers ----
__device__ __forceinline__ void cp_async16(void* dst, const void* src) {
    unsigned s = (unsigned)__cvta_generic_to_shared(dst);
    asm volatile("cp.async.cg.shared.global [%0], [%1], 16;" :: "r"(s), "l"(src));
}
__device__ __forceinline__ void cp_commit() {
    asm volatile("cp.async.commit_group;" ::: "memory");
}
template <int NN> __device__ __forceinline__ void cp_wait() {
    asm volatile("cp.async.wait_group %0;" :: "n"(NN) : "memory");
}

// ---- tf32 mma helpers ----
__device__ __forceinline__ uint32_t f2tf(float x) {
    uint32_t r; asm("cvt.rna.tf32.f32 %0, %1;" : "=r"(r) : "f"(x)); return r;
}
__device__ __forceinline__ void mma_tf32(float* c, const uint32_t* a, const uint32_t* b) {
    asm("mma.sync.aligned.m16n8k8.row.col.f32.tf32.tf32.f32 "
        "{%0,%1,%2,%3},{%4,%5,%6,%7},{%8,%9},{%0,%1,%2,%3};"
        : "+f"(c[0]), "+f"(c[1]), "+f"(c[2]), "+f"(c[3])
        : "r"(a[0]), "r"(a[1]), "r"(a[2]), "r"(a[3]), "r"(b[0]), "r"(b[1]));
}

// ---------------- device scratch -------------------------------------------------
__device__ float g_xw [(size_t)N_ * T_ * G4];          // phase1 out: [n][t][2048]
__device__ float g_xw2[(size_t)T_ * NB * 512];         // [t][cta][n8][gate][j16]
__device__ float g_hT [(size_t)(T_ + 1) * 4 * 4096];   // h history: [t][g][k(512)][n8(8)]
__device__ unsigned int g_cnt[16 * 64];                // [g*4+sub]*64: subgroup counters

// ---------------- init: counters + h0 -> g_hT[0] ----------------------------------
__global__ void init_state_kernel(const float* __restrict__ h0)
{
    int i = blockIdx.x * blockDim.x + threadIdx.x;
    if (i < 16) g_cnt[i * 64] = 0u;
    if (i < 4 * 512 * 8) {
        int g = i >> 12, k = (i >> 3) & 511, n8 = i & 7;
        g_hT[(size_t)g * 4096 + k * 8 + n8] = h0[(size_t)(g * 8 + n8) * H_ + k];
    }
}

// ---------------- Phase 1: xw = x @ Wx + b  via tf32 tensor cores ------------------
#define AS_STR 40
#define BS_STR 132
#define AS_BUF (128 * AS_STR)
#define BS_BUF (32 * BS_STR)

__global__ __launch_bounds__(256) void gemm_xw_tc(const float* __restrict__ x,
                                                  const float* __restrict__ Wx,
                                                  const float* __restrict__ bias)
{
    extern __shared__ float sm1[];
    float* As = sm1;
    float* Bs = sm1 + 2 * AS_BUF;

    const int tid  = threadIdx.x;
    const int bn   = blockIdx.x, bm = blockIdx.y;
    const int warp = tid >> 5, lane = tid & 31;
    const int wy = warp & 1, wx = warp >> 1;
    const int g  = lane >> 2, tg = lane & 3;

    float acc[4][4][4];
#pragma unroll
    for (int mi = 0; mi < 4; mi++)
#pragma unroll
        for (int ni = 0; ni < 4; ni++)
#pragma unroll
            for (int c = 0; c < 4; c++) acc[mi][ni][c] = 0.f;

    {
#pragma unroll
        for (int i = 0; i < 4; i++) {
            int flat = i * 256 + tid;
            int m = flat >> 3, kc = flat & 7;
            cp_async16(As + m * AS_STR + kc * 4,
                       x + (size_t)(bm * 128 + m) * D_ + kc * 4);
        }
#pragma unroll
        for (int i = 0; i < 4; i++) {
            int flat = i * 256 + tid;
            int k = flat >> 5, nc = flat & 31;
            cp_async16(Bs + k * BS_STR + nc * 4,
                       Wx + (size_t)k * G4 + bn * 128 + nc * 4);
        }
        cp_commit();
    }

    for (int it = 0; it < 16; it++) {
        if (it < 15) {
            const int k0 = (it + 1) * 32;
            const int nb = (it + 1) & 1;
#pragma unroll
            for (int i = 0; i < 4; i++) {
                int flat = i * 256 + tid;
                int m = flat >> 3, kc = flat & 7;
                cp_async16(As + nb * AS_BUF + m * AS_STR + kc * 4,
                           x + (size_t)(bm * 128 + m) * D_ + k0 + kc * 4);
            }
#pragma unroll
            for (int i = 0; i < 4; i++) {
                int flat = i * 256 + tid;
                int k = flat >> 5, nc = flat & 31;
                cp_async16(Bs + nb * BS_BUF + k * BS_STR + nc * 4,
                           Wx + (size_t)(k0 + k) * G4 + bn * 128 + nc * 4);
            }
            cp_commit();
            cp_wait<1>();
        } else {
            cp_wait<0>();
        }
        __syncthreads();

        const float* Ab = As + (it & 1) * AS_BUF;
        const float* Bb = Bs + (it & 1) * BS_BUF;
#pragma unroll
        for (int ks = 0; ks < 4; ks++) {
            uint32_t af[4][4], bf[4][2];
#pragma unroll
            for (int mi = 0; mi < 4; mi++) {
                const float* ap_ = Ab + (wy * 64 + mi * 16) * AS_STR + ks * 8;
                af[mi][0] = f2tf(ap_[ g      * AS_STR + tg    ]);
                af[mi][1] = f2tf(ap_[(g + 8) * AS_STR + tg    ]);
                af[mi][2] = f2tf(ap_[ g      * AS_STR + tg + 4]);
                af[mi][3] = f2tf(ap_[(g + 8) * AS_STR + tg + 4]);
            }
#pragma unroll
            for (int ni = 0; ni < 4; ni++) {
                const float* bp_ = Bb + ks * 8 * BS_STR + wx * 32 + ni * 8 + g;
                bf[ni][0] = f2tf(bp_[ tg      * BS_STR]);
                bf[ni][1] = f2tf(bp_[(tg + 4) * BS_STR]);
            }
#pragma unroll
            for (int mi = 0; mi < 4; mi++)
#pragma unroll
                for (int ni = 0; ni < 4; ni++)
                    mma_tf32(acc[mi][ni], af[mi], bf[ni]);
        }
        __syncthreads();
    }

#pragma unroll
    for (int ni = 0; ni < 4; ni++) {
        int col = bn * 128 + wx * 32 + ni * 8 + 2 * tg;
        float b0 = bias[col], b1 = bias[col + 1];
#pragma unroll
        for (int mi = 0; mi < 4; mi++) {
            int row0 = bm * 128 + wy * 64 + mi * 16 + g;
            float2 v0; v0.x = acc[mi][ni][0] + b0; v0.y = acc[mi][ni][1] + b1;
            float2 v1; v1.x = acc[mi][ni][2] + b0; v1.y = acc[mi][ni][3] + b1;
            *(float2*)(g_xw + (size_t)row0 * G4 + col)       = v0;
            *(float2*)(g_xw + (size_t)(row0 + 8) * G4 + col) = v1;
        }
    }
}

// ---------------- T1: g_xw[n][t][2048] -> g_xw2[t][cta][n8][gate][j16] -------------
__global__ __launch_bounds__(512) void xw_transpose_kernel()
{
    const int t = blockIdx.x;
    const int g = blockIdx.y;
#pragma unroll
    for (int it = 0; it < 8; it++) {
        int flat = it * 512 + threadIdx.x;
        int r    = flat >> 7;
        int n8   = (flat >> 4) & 7;
        int gate = (flat >> 2) & 3;
        int jl4  = flat & 3;
        float4 v = __ldcg((const float4*)(g_xw +
                    ((size_t)(g * 8 + n8) * T_ + t) * G4 + gate * 512 + r * 16 + jl4 * 4));
        *(float4*)(g_xw2 + (((size_t)t * NB + g * 32 + r) * 8 + n8) * 64
                         + gate * 16 + jl4 * 4) = v;
    }
}

// ---------------- Phase 2: per-group persistent, subgroup-counter sync -------------
extern __shared__ float smem_dyn[];

__global__ __launch_bounds__(NTH, 1) void lstm_rec_kernel(const float* __restrict__ Wh)
{
    float* ws = smem_dyn;                       // [512][64]
    float* hs = ws + 512 * 64;                  // [512][8]
    ull*   ap = (ull*)(hs + 512 * 8);           // [16][APW]

    const int b   = blockIdx.x;
    const int g   = b >> 5;          // group 0..3 (batch n = g*8..g*8+7)
    const int r   = b & 31;          // rank: j-columns [r*16, r*16+16)
    const int tid = threadIdx.x;

    for (int idx = tid; idx < 512 * 64; idx += NTH) {
        int k = idx >> 6, c = idx & 63;
        ws[idx] = Wh[(size_t)k * G4 + (c >> 4) * 512 + r * 16 + (c & 15)];
    }
    __syncthreads();

    if (tid < 512) {
        // ================= GEMM worker warps =================
        const int w    = tid >> 5;
        const int lane = tid & 31;
        const int kg   = lane >> 4;
        const int pos  = lane & 15;
        const int cg4  = pos * 4;
        const int kbase = w * 32 + kg * 16;
        // producers of my k-slice: ranks 2w, 2w+1 -> subgroup w>>2
        const unsigned* prodp = &g_cnt[(g * 4 + (w >> 2)) * 64];
        // own rank's subgroup (protects ap WAR; checked after compute)
        const unsigned* ownp  = &g_cnt[(g * 4 + (r >> 3)) * 64];

        for (int t = 0; t < T_; t++) {
            if (t > 0) {
                unsigned target = 8u * (unsigned)t, v;
                do {
                    asm volatile("ld.acquire.gpu.global.u32 %0, [%1];"
                                 : "=r"(v) : "l"(prodp) : "memory");
                } while (v < target);
            }
            // stage own k-slice of h (two float4 per lane)
            const float* hb = g_hT + ((size_t)t * 4 + g) * 4096;
            {
                int off = (w * 32 + (lane >> 1)) * 8 + (lane & 1) * 4;
                float4 v0 = __ldcg((const float4*)(hb + off));
                float4 v1 = __ldcg((const float4*)(hb + off + 128));
                *(float4*)(hs + off) = v0;
                *(float4*)(hs + off + 128) = v1;
            }
            __syncwarp();

            ull acc[4][4];
#pragma unroll
            for (int u = 0; u < 4; u++)
#pragma unroll
                for (int c = 0; c < 4; c++) acc[u][c] = 0ULL;

#pragma unroll
            for (int i = 0; i < 16; i++) {
                int k = kbase + i;
                ulonglong2 hA = *(const ulonglong2*)(hs + k * 8);
                ulonglong2 hB = *(const ulonglong2*)(hs + k * 8 + 4);
                ull hv[4] = {hA.x, hA.y, hB.x, hB.y};
                float4 wf = *(const float4*)(ws + k * 64 + cg4);
                ull wb[4] = {bcast2(wf.x), bcast2(wf.y), bcast2(wf.z), bcast2(wf.w)};
#pragma unroll
                for (int u = 0; u < 4; u++)
#pragma unroll
                    for (int c = 0; c < 4; c++)
                        fma2(acc[u][c], hv[u], wb[c]);
            }
#pragma unroll
            for (int u = 0; u < 4; u++)
#pragma unroll
                for (int c = 0; c < 4; c++) {
                    ull o = __shfl_xor_sync(0xFFFFFFFFu, acc[u][c], 16);
                    add2(acc[u][c], o);
                }
            // deferred own-reduce check: ap(t-1) must be drained before overwrite
            if (t > 0) {
                unsigned target = 8u * (unsigned)t, v;
                do {
                    asm volatile("ld.acquire.gpu.global.u32 %0, [%1];"
                                 : "=r"(v) : "l"(ownp) : "memory");
                } while (v < target);
            }
            if (kg == 0) {
                ull* pl = ap + w * APW;
#pragma unroll
                for (int u = 0; u < 4; u++) {
                    ulonglong2 s0, s1;
                    s0.x = acc[u][0]; s0.y = acc[u][1];
                    s1.x = acc[u][2]; s1.y = acc[u][3];
                    *(ulonglong2*)(pl + u * 72 + cg4)     = s0;
                    *(ulonglong2*)(pl + u * 72 + cg4 + 2) = s1;
                }
            }
            asm volatile("membar.cta;");
            asm volatile("bar.arrive 1, %0;" :: "n"(NTH));
        }
    } else {
        // ================= reduce / gates warps (tid 512..575) =================
        const int rt = tid - 512;
        const int np = rt >> 4, jc = rt & 15;

        float c0v = 0.f, c1v = 0.f;
        float xwr[2][4];
        {
            const float* xb = g_xw2 + (size_t)b * 512;
#pragma unroll
            for (int rr = 0; rr < 2; rr++)
#pragma unroll
                for (int q = 0; q < 4; q++)
                    xwr[rr][q] = __ldcg(xb + (2 * np + rr) * 64 + q * 16 + jc);
        }

        for (int t = 0; t < T_; t++) {
            asm volatile("bar.sync 1, %0;" :: "n"(NTH));

            ull s0 = 0ULL, s1 = 0ULL, s2 = 0ULL, s3 = 0ULL;
            const ull* base = ap + np * 72 + jc;
#pragma unroll
            for (int p = 0; p < 16; p++) {
                const ull* pl = base + p * APW;
                add2(s0, pl[0]);
                add2(s1, pl[16]);
                add2(s2, pl[32]);
                add2(s3, pl[48]);
            }
            float a0l, a0h, a1l, a1h, a2l, a2h, a3l, a3h;
            unpack2(a0l, a0h, s0);
            unpack2(a1l, a1h, s1);
            unpack2(a2l, a2h, s2);
            unpack2(a3l, a3h, s3);

            float ig0 = fsig(a0l + xwr[0][0]);
            float fg0 = fsig(a1l + xwr[0][1]);
            float og0 = fsig(a2l + xwr[0][2]);
            float gg0 = ftanh(a3l + xwr[0][3]);
            c0v = fg0 * c0v + ig0 * gg0;
            float hn0 = og0 * ftanh(c0v);

            float ig1 = fsig(a0h + xwr[1][0]);
            float fg1 = fsig(a1h + xwr[1][1]);
            float og1 = fsig(a2h + xwr[1][2]);
            float gg1 = ftanh(a3h + xwr[1][3]);
            c1v = fg1 * c1v + ig1 * gg1;
            float hn1 = og1 * ftanh(c1v);

            // publish h(t+1) straight to L2
            {
                float* dst = g_hT + ((size_t)(t + 1) * 4 + g) * 4096 + (r * 16 + jc) * 8 + 2 * np;
                asm volatile("st.global.cg.v2.f32 [%0], {%1, %2};"
                             :: "l"(dst), "f"(hn0), "f"(hn1) : "memory");
            }
            asm volatile("bar.sync 2, 64;");
            if (rt == 0) {
                __threadfence();
                atomicAdd(&g_cnt[(g * 4 + (r >> 3)) * 64], 1u);
            }
            // off critical path: next xw prefetch
            if (t + 1 < T_) {
                const float* xb = g_xw2 + ((size_t)(t + 1) * NB + b) * 512;
#pragma unroll
                for (int rr = 0; rr < 2; rr++)
#pragma unroll
                    for (int q = 0; q < 4; q++)
                        xwr[rr][q] = __ldcg(xb + (2 * np + rr) * 64 + q * 16 + jc);
            }
        }
    }
}

// ---------------- T2: g_hT[t+1][g][j][n8] -> out[n][t][j] --------------------------
__global__ __launch_bounds__(512) void out_transpose_kernel(float* __restrict__ out)
{
    extern __shared__ float sm[];
    const int t = blockIdx.x;
    const int tid = threadIdx.x;
    const float* src = g_hT + (size_t)(t + 1) * 4 * 4096;
#pragma unroll
    for (int it = 0; it < 8; it++) {
        int idx = tid + it * 512;
        *(float4*)(sm + idx * 4) = __ldcg((const float4*)(src + idx * 4));
    }
    __syncthreads();
    const int n = tid >> 4, jb = (tid & 15) * 32;
    const int gbase = (n >> 3) * 4096, n8 = n & 7;
#pragma unroll
    for (int it = 0; it < 8; it++) {
        int j = jb + it * 4;
        float4 v;
        v.x = sm[gbase + (j + 0) * 8 + n8];
        v.y = sm[gbase + (j + 1) * 8 + n8];
        v.z = sm[gbase + (j + 2) * 8 + n8];
        v.w = sm[gbase + (j + 3) * 8 + n8];
        *(float4*)(out + ((size_t)n * T_ + t) * H_ + j) = v;
    }
}

// ---------------- launch ----------------------------------------------------------
extern "C" void kernel_launch(void* const* d_in, const int* in_sizes, int n_in,
                              void* d_out, int out_size)
{
    const float* x    = (const float*)d_in[0];
    const float* h0   = (const float*)d_in[1];
    const float* Wx   = (const float*)d_in[2];
    const float* Wh   = (const float*)d_in[3];
    const float* bias = (const float*)d_in[4];
    float* out = (float*)d_out;

    init_state_kernel<<<64, 256>>>(h0);

    const int sh1 = (2 * AS_BUF + 2 * BS_BUF) * (int)sizeof(float);
    cudaFuncSetAttribute(gemm_xw_tc, cudaFuncAttributeMaxDynamicSharedMemorySize, sh1);
    dim3 g1(G4 / 128, (N_ * T_) / 128);
    gemm_xw_tc<<<g1, 256, sh1>>>(x, Wx, bias);

    dim3 gt1(T_, 4);
    xw_transpose_kernel<<<gt1, 512>>>();

    const int shmem = (512 * 64 + 512 * 8) * 4 + 16 * APW * 8;
    cudaFuncSetAttribute(lstm_rec_kernel, cudaFuncAttributeMaxDynamicSharedMemorySize, shmem);
    lstm_rec_kernel<<<NB, NTH, shmem>>>(Wh);

    cudaFuncSetAttribute(out_transpose_kernel, cudaFuncAttributeMaxDynamicSharedMemorySize, 65536);
    out_transpose_kernel<<<T_, 512, 65536>>>(out);
}

// round 16
// speedup vs baseline: 3.5913x; 1.0449x over previous
#include <cuda_runtime.h>
#include <cuda_bf16.h>
#include <cstdint>
#include <math.h>

#define N_  32
#define T_  1024
#define D_  512
#define H_  512
#define G4  2048

#define NB   128
#define NTH  576    // 16 GEMM warps + 2 reduce warps
#define APW  288    // partial plane stride (ull): 4 np * 72

typedef unsigned long long ull;
typedef unsigned short u16;
typedef unsigned int u32;

__device__ __forceinline__ void add2(ull& d, const ull a) {
    asm("add.rn.f32x2 %0, %0, %1;" : "+l"(d) : "l"(a));
}
__device__ __forceinline__ void unpack2(float& lo, float& hi, ull a) {
    asm("mov.b64 {%0, %1}, %2;" : "=f"(lo), "=f"(hi) : "l"(a));
}
__device__ __forceinline__ ull pack2(float lo, float hi) {
    ull r; asm("mov.b64 %0, {%1, %2};" : "=l"(r) : "f"(lo), "f"(hi)); return r;
}
__device__ __forceinline__ float fsig(float x) { return 1.f / (1.f + __expf(-x)); }
__device__ __forceinline__ float ftanh(float x) { return 2.f / (1.f + __expf(-2.f * x)) - 1.f; }
__device__ __forceinline__ float bf2f(u16 b) { return __uint_as_float((u32)b << 16); }

// ---- cp.async helpers ----
__device__ __forceinline__ void cp_async16(void* dst, const void* src) {
    unsigned s = (unsigned)__cvta_generic_to_shared(dst);
    asm volatile("cp.async.cg.shared.global [%0], [%1], 16;" :: "r"(s), "l"(src));
}
__device__ __forceinline__ void cp_commit() {
    asm volatile("cp.async.commit_group;" ::: "memory");
}
template <int NN> __device__ __forceinline__ void cp_wait() {
    asm volatile("cp.async.wait_group %0;" :: "n"(NN) : "memory");
}

// ---- tf32 mma (phase 1) ----
__device__ __forceinline__ uint32_t f2tf(float x) {
    uint32_t r; asm("cvt.rna.tf32.f32 %0, %1;" : "=r"(r) : "f"(x)); return r;
}
__device__ __forceinline__ void mma_tf32(float* c, const uint32_t* a, const uint32_t* b) {
    asm("mma.sync.aligned.m16n8k8.row.col.f32.tf32.tf32.f32 "
        "{%0,%1,%2,%3},{%4,%5,%6,%7},{%8,%9},{%0,%1,%2,%3};"
        : "+f"(c[0]), "+f"(c[1]), "+f"(c[2]), "+f"(c[3])
        : "r"(a[0]), "r"(a[1]), "r"(a[2]), "r"(a[3]), "r"(b[0]), "r"(b[1]));
}

// ---- bf16 mma (phase 2) ----
__device__ __forceinline__ void mma_bf16(float* c, const u32* a, const u32* b) {
    asm("mma.sync.aligned.m16n8k16.row.col.f32.bf16.bf16.f32 "
        "{%0,%1,%2,%3},{%4,%5,%6,%7},{%8,%9},{%0,%1,%2,%3};"
        : "+f"(c[0]), "+f"(c[1]), "+f"(c[2]), "+f"(c[3])
        : "r"(a[0]), "r"(a[1]), "r"(a[2]), "r"(a[3]), "r"(b[0]), "r"(b[1]));
}
__device__ __forceinline__ void ldmx4(u32* r, u32 saddr) {
    asm volatile("ldmatrix.sync.aligned.m8n8.x4.shared.b16 {%0,%1,%2,%3}, [%4];"
                 : "=r"(r[0]), "=r"(r[1]), "=r"(r[2]), "=r"(r[3]) : "r"(saddr));
}
__device__ __forceinline__ void ldmx2t(u32* r, u32 saddr) {
    asm volatile("ldmatrix.sync.aligned.m8n8.x2.trans.shared.b16 {%0,%1}, [%2];"
                 : "=r"(r[0]), "=r"(r[1]) : "r"(saddr));
}

// ---------------- device scratch -------------------------------------------------
__device__ float g_xw [(size_t)N_ * T_ * G4];          // phase1 out: [n][t][2048]
__device__ float g_xw2[(size_t)T_ * NB * 512];         // [t][cta][n8][gate][j16]
__device__ u16   g_hHi[(size_t)(T_ + 1) * 4 * 4096];   // h hi bf16: [t][g][k][n8]
__device__ u16   g_hLo[(size_t)(T_ + 1) * 4 * 4096];   // h lo bf16
__device__ unsigned int g_cnt[16 * 64];                // subgroup counters

// ---------------- init: counters + h0 -> hi/lo -------------------------------------
__global__ void init_state_kernel(const float* __restrict__ h0)
{
    int i = blockIdx.x * blockDim.x + threadIdx.x;
    if (i < 16) g_cnt[i * 64] = 0u;
    if (i < 4 * 512 * 8) {
        int g = i >> 12, k = (i >> 3) & 511, n8 = i & 7;
        float v = h0[(size_t)(g * 8 + n8) * H_ + k];
        __nv_bfloat16 bh = __float2bfloat16(v);
        __nv_bfloat16 bl = __float2bfloat16(v - __bfloat162float(bh));
        size_t off = (size_t)g * 4096 + k * 8 + n8;
        g_hHi[off] = *reinterpret_cast<u16*>(&bh);
        g_hLo[off] = *reinterpret_cast<u16*>(&bl);
    }
}

// ---------------- Phase 1: xw = x @ Wx + b  via tf32 tensor cores ------------------
#define AS_STR 40
#define BS_STR 132
#define AS_BUF (128 * AS_STR)
#define BS_BUF (32 * BS_STR)

__global__ __launch_bounds__(256) void gemm_xw_tc(const float* __restrict__ x,
                                                  const float* __restrict__ Wx,
                                                  const float* __restrict__ bias)
{
    extern __shared__ float sm1[];
    float* As = sm1;
    float* Bs = sm1 + 2 * AS_BUF;

    const int tid  = threadIdx.x;
    const int bn   = blockIdx.x, bm = blockIdx.y;
    const int warp = tid >> 5, lane = tid & 31;
    const int wy = warp & 1, wx = warp >> 1;
    const int g  = lane >> 2, tg = lane & 3;

    float acc[4][4][4];
#pragma unroll
    for (int mi = 0; mi < 4; mi++)
#pragma unroll
        for (int ni = 0; ni < 4; ni++)
#pragma unroll
            for (int c = 0; c < 4; c++) acc[mi][ni][c] = 0.f;

    {
#pragma unroll
        for (int i = 0; i < 4; i++) {
            int flat = i * 256 + tid;
            int m = flat >> 3, kc = flat & 7;
            cp_async16(As + m * AS_STR + kc * 4,
                       x + (size_t)(bm * 128 + m) * D_ + kc * 4);
        }
#pragma unroll
        for (int i = 0; i < 4; i++) {
            int flat = i * 256 + tid;
            int k = flat >> 5, nc = flat & 31;
            cp_async16(Bs + k * BS_STR + nc * 4,
                       Wx + (size_t)k * G4 + bn * 128 + nc * 4);
        }
        cp_commit();
    }

    for (int it = 0; it < 16; it++) {
        if (it < 15) {
            const int k0 = (it + 1) * 32;
            const int nb = (it + 1) & 1;
#pragma unroll
            for (int i = 0; i < 4; i++) {
                int flat = i * 256 + tid;
                int m = flat >> 3, kc = flat & 7;
                cp_async16(As + nb * AS_BUF + m * AS_STR + kc * 4,
                           x + (size_t)(bm * 128 + m) * D_ + k0 + kc * 4);
            }
#pragma unroll
            for (int i = 0; i < 4; i++) {
                int flat = i * 256 + tid;
                int k = flat >> 5, nc = flat & 31;
                cp_async16(Bs + nb * BS_BUF + k * BS_STR + nc * 4,
                           Wx + (size_t)(k0 + k) * G4 + bn * 128 + nc * 4);
            }
            cp_commit();
            cp_wait<1>();
        } else {
            cp_wait<0>();
        }
        __syncthreads();

        const float* Ab = As + (it & 1) * AS_BUF;
        const float* Bb = Bs + (it & 1) * BS_BUF;
#pragma unroll
        for (int ks = 0; ks < 4; ks++) {
            uint32_t af[4][4], bf[4][2];
#pragma unroll
            for (int mi = 0; mi < 4; mi++) {
                const float* ap_ = Ab + (wy * 64 + mi * 16) * AS_STR + ks * 8;
                af[mi][0] = f2tf(ap_[ g      * AS_STR + tg    ]);
                af[mi][1] = f2tf(ap_[(g + 8) * AS_STR + tg    ]);
                af[mi][2] = f2tf(ap_[ g      * AS_STR + tg + 4]);
                af[mi][3] = f2tf(ap_[(g + 8) * AS_STR + tg + 4]);
            }
#pragma unroll
            for (int ni = 0; ni < 4; ni++) {
                const float* bp_ = Bb + ks * 8 * BS_STR + wx * 32 + ni * 8 + g;
                bf[ni][0] = f2tf(bp_[ tg      * BS_STR]);
                bf[ni][1] = f2tf(bp_[(tg + 4) * BS_STR]);
            }
#pragma unroll
            for (int mi = 0; mi < 4; mi++)
#pragma unroll
                for (int ni = 0; ni < 4; ni++)
                    mma_tf32(acc[mi][ni], af[mi], bf[ni]);
        }
        __syncthreads();
    }

#pragma unroll
    for (int ni = 0; ni < 4; ni++) {
        int col = bn * 128 + wx * 32 + ni * 8 + 2 * tg;
        float b0 = bias[col], b1 = bias[col + 1];
#pragma unroll
        for (int mi = 0; mi < 4; mi++) {
            int row0 = bm * 128 + wy * 64 + mi * 16 + g;
            float2 v0; v0.x = acc[mi][ni][0] + b0; v0.y = acc[mi][ni][1] + b1;
            float2 v1; v1.x = acc[mi][ni][2] + b0; v1.y = acc[mi][ni][3] + b1;
            *(float2*)(g_xw + (size_t)row0 * G4 + col)       = v0;
            *(float2*)(g_xw + (size_t)(row0 + 8) * G4 + col) = v1;
        }
    }
}

// ---------------- T1: g_xw[n][t][2048] -> g_xw2[t][cta][n8][gate][j16] -------------
__global__ __launch_bounds__(512) void xw_transpose_kernel()
{
    const int t = blockIdx.x;
    const int g = blockIdx.y;
#pragma unroll
    for (int it = 0; it < 8; it++) {
        int flat = it * 512 + threadIdx.x;
        int r    = flat >> 7;
        int n8   = (flat >> 4) & 7;
        int gate = (flat >> 2) & 3;
        int jl4  = flat & 3;
        float4 v = __ldcg((const float4*)(g_xw +
                    ((size_t)(g * 8 + n8) * T_ + t) * G4 + gate * 512 + r * 16 + jl4 * 4));
        *(float4*)(g_xw2 + (((size_t)t * NB + g * 32 + r) * 8 + n8) * 64
                         + gate * 16 + jl4 * 4) = v;
    }
}

// ---------------- Phase 2: persistent, bf16-split tensor-core GEMM -----------------
extern __shared__ float smem_dyn[];

__global__ __launch_bounds__(NTH, 1) void lstm_rec_kernel(const float* __restrict__ Wh)
{
    // smem (ushort units): wsh[32768] | wsl[32768] | hsh[4096] | hsl[4096] | ap
    u16* wsh = (u16*)smem_dyn;            // tiled: [(m*32+kt)*256 + c16*16 + k16]
    u16* wsl = wsh + 32768;
    u16* hsh = wsl + 32768;               // [k][n8], 16B rows
    u16* hsl = hsh + 4096;
    ull* ap  = (ull*)(hsl + 4096);        // [16][APW]

    const int b   = blockIdx.x;
    const int grp = b >> 5;          // group 0..3 (batch n = grp*8..grp*8+7)
    const int r   = b & 31;          // rank: j-columns [r*16, r*16+16)
    const int tid = threadIdx.x;

    // weights -> bf16 hi/lo, tiled 16x16 (512B contiguous tiles)
    for (int idx = tid; idx < 64 * 512; idx += NTH) {
        int c = idx >> 9, k = idx & 511;
        float w = Wh[(size_t)k * G4 + (c >> 4) * 512 + r * 16 + (c & 15)];
        __nv_bfloat16 bh = __float2bfloat16(w);
        __nv_bfloat16 bl = __float2bfloat16(w - __bfloat162float(bh));
        int off = ((c >> 4) * 32 + (k >> 4)) * 256 + (c & 15) * 16 + (k & 15);
        wsh[off] = *reinterpret_cast<u16*>(&bh);
        wsl[off] = *reinterpret_cast<u16*>(&bl);
    }
    __syncthreads();

    if (tid < 512) {
        // ================= GEMM worker warps (tensor core) =================
        const int w    = tid >> 5;
        const int lane = tid & 31;
        const int gq   = lane >> 2, tg = lane & 3;
        const unsigned* prodp = &g_cnt[(grp * 4 + (w >> 2)) * 64];
        const unsigned* ownp  = &g_cnt[(grp * 4 + (r >> 3)) * 64];

        // B ldmatrix addresses (fixed): thread row = w*32 + kt*16 + (lane&15)
        const u32 bAh = (u32)__cvta_generic_to_shared(hsh + (w * 32 + (lane & 15)) * 8);
        const u32 bAl = (u32)__cvta_generic_to_shared(hsl + (w * 32 + (lane & 15)) * 8);
        // A ldmatrix per-thread offset within a tile (bytes)
        const u32 aTh = (lane & 15) * 32 + (lane >> 4) * 16;
        const u32 wshS = (u32)__cvta_generic_to_shared(wsh);
        const u32 wslS = (u32)__cvta_generic_to_shared(wsl);

        for (int t = 0; t < T_; t++) {
            if (t > 0) {
                unsigned target = 8u * (unsigned)t, v;
                do {
                    asm volatile("ld.acquire.gpu.global.u32 %0, [%1];"
                                 : "=r"(v) : "l"(prodp) : "memory");
                } while (v < target);
            }
            // stage own 32 k-rows of h (hi+lo), 16B per row, one row per lane
            {
                int row = w * 32 + lane;
                size_t hoff = ((size_t)t * 4 + grp) * 4096 + row * 8;
                uint4 vh = __ldcg((const uint4*)(g_hHi + hoff));
                uint4 vl = __ldcg((const uint4*)(g_hLo + hoff));
                *(uint4*)(hsh + row * 8) = vh;
                *(uint4*)(hsl + row * 8) = vl;
            }
            __syncwarp();

            // B fragments for this warp's 2 k-tiles
            u32 bh[2][2], bl[2][2];
            ldmx2t(bh[0], bAh);
            ldmx2t(bh[1], bAh + 256);
            ldmx2t(bl[0], bAl);
            ldmx2t(bl[1], bAl + 256);

            float acc[4][4];
#pragma unroll
            for (int m = 0; m < 4; m++)
#pragma unroll
                for (int c = 0; c < 4; c++) acc[m][c] = 0.f;

#pragma unroll
            for (int m = 0; m < 4; m++) {
#pragma unroll
                for (int kt = 0; kt < 2; kt++) {
                    u32 tileOff = (u32)((m * 32 + 2 * w + kt) * 512) + aTh;
                    u32 ah[4], al[4];
                    ldmx4(ah, wshS + tileOff);
                    ldmx4(al, wslS + tileOff);
                    mma_bf16(acc[m], ah, bh[kt]);
                    mma_bf16(acc[m], ah, bl[kt]);
                    mma_bf16(acc[m], al, bh[kt]);
                }
            }

            // deferred own-reduce check (ap WAR)
            if (t > 0) {
                unsigned target = 8u * (unsigned)t, v;
                do {
                    asm volatile("ld.acquire.gpu.global.u32 %0, [%1];"
                                 : "=r"(v) : "l"(ownp) : "memory");
                } while (v < target);
            }
            // store partials: np = tg, c = m*16 + gq (+8)
            {
                ull* pl = ap + w * APW + tg * 72;
#pragma unroll
                for (int m = 0; m < 4; m++) {
                    pl[m * 16 + gq]     = pack2(acc[m][0], acc[m][1]);
                    pl[m * 16 + gq + 8] = pack2(acc[m][2], acc[m][3]);
                }
            }
            asm volatile("membar.cta;");
            asm volatile("bar.arrive 1, %0;" :: "n"(NTH));
        }
    } else {
        // ================= reduce / gates warps (tid 512..575) =================
        const int rt = tid - 512;
        const int np = rt >> 4, jc = rt & 15;

        float c0v = 0.f, c1v = 0.f;
        float xwr[2][4];
        {
            const float* xb = g_xw2 + (size_t)b * 512;
#pragma unroll
            for (int rr = 0; rr < 2; rr++)
#pragma unroll
                for (int q = 0; q < 4; q++)
                    xwr[rr][q] = __ldcg(xb + (2 * np + rr) * 64 + q * 16 + jc);
        }

        for (int t = 0; t < T_; t++) {
            asm volatile("bar.sync 1, %0;" :: "n"(NTH));

            ull s0 = 0ULL, s1 = 0ULL, s2 = 0ULL, s3 = 0ULL;
            const ull* base = ap + np * 72 + jc;
#pragma unroll
            for (int p = 0; p < 16; p++) {
                const ull* pl = base + p * APW;
                add2(s0, pl[0]);
                add2(s1, pl[16]);
                add2(s2, pl[32]);
                add2(s3, pl[48]);
            }
            float a0l, a0h, a1l, a1h, a2l, a2h, a3l, a3h;
            unpack2(a0l, a0h, s0);
            unpack2(a1l, a1h, s1);
            unpack2(a2l, a2h, s2);
            unpack2(a3l, a3h, s3);

            float ig0 = fsig(a0l + xwr[0][0]);
            float fg0 = fsig(a1l + xwr[0][1]);
            float og0 = fsig(a2l + xwr[0][2]);
            float gg0 = ftanh(a3l + xwr[0][3]);
            c0v = fg0 * c0v + ig0 * gg0;
            float hn0 = og0 * ftanh(c0v);

            float ig1 = fsig(a0h + xwr[1][0]);
            float fg1 = fsig(a1h + xwr[1][1]);
            float og1 = fsig(a2h + xwr[1][2]);
            float gg1 = ftanh(a3h + xwr[1][3]);
            c1v = fg1 * c1v + ig1 * gg1;
            float hn1 = og1 * ftanh(c1v);

            // publish h(t+1) as bf16 hi/lo pairs (4B each)
            {
                __nv_bfloat16 h0b = __float2bfloat16(hn0);
                __nv_bfloat16 h1b = __float2bfloat16(hn1);
                __nv_bfloat16 l0b = __float2bfloat16(hn0 - __bfloat162float(h0b));
                __nv_bfloat16 l1b = __float2bfloat16(hn1 - __bfloat162float(h1b));
                u32 hiP = (u32)*reinterpret_cast<u16*>(&h0b) |
                          ((u32)*reinterpret_cast<u16*>(&h1b) << 16);
                u32 loP = (u32)*reinterpret_cast<u16*>(&l0b) |
                          ((u32)*reinterpret_cast<u16*>(&l1b) << 16);
                size_t off = ((size_t)(t + 1) * 4 + grp) * 4096 + (r * 16 + jc) * 8 + 2 * np;
                asm volatile("st.global.cg.u32 [%0], %1;" :: "l"(g_hHi + off), "r"(hiP) : "memory");
                asm volatile("st.global.cg.u32 [%0], %1;" :: "l"(g_hLo + off), "r"(loP) : "memory");
            }
            asm volatile("bar.sync 2, 64;");
            if (rt == 0) {
                __threadfence();
                atomicAdd(&g_cnt[(grp * 4 + (r >> 3)) * 64], 1u);
            }
            if (t + 1 < T_) {
                const float* xb = g_xw2 + ((size_t)(t + 1) * NB + b) * 512;
#pragma unroll
                for (int rr = 0; rr < 2; rr++)
#pragma unroll
                    for (int q = 0; q < 4; q++)
                        xwr[rr][q] = __ldcg(xb + (2 * np + rr) * 64 + q * 16 + jc);
            }
        }
    }
}

// ---------------- T2: hi/lo -> out[n][t][j] ----------------------------------------
__global__ __launch_bounds__(512) void out_transpose_kernel(float* __restrict__ out)
{
    extern __shared__ float sm[];
    const int t = blockIdx.x;
    const int tid = threadIdx.x;
#pragma unroll
    for (int it = 0; it < 4; it++) {
        int gr = tid + it * 512;            // global row: g*512 + k
        int g = gr >> 9, k = gr & 511;
        size_t off = ((size_t)(t + 1) * 4 + g) * 4096 + k * 8;
        uint4 vh = __ldcg((const uint4*)(g_hHi + off));
        uint4 vl = __ldcg((const uint4*)(g_hLo + off));
        float* dst = sm + g * 4096 + k * 8;
        u32 hw[4] = {vh.x, vh.y, vh.z, vh.w};
        u32 lw[4] = {vl.x, vl.y, vl.z, vl.w};
#pragma unroll
        for (int q = 0; q < 4; q++) {
            dst[2 * q]     = __uint_as_float(hw[q] << 16) + __uint_as_float(lw[q] << 16);
            dst[2 * q + 1] = __uint_as_float(hw[q] & 0xFFFF0000u) +
                             __uint_as_float(lw[q] & 0xFFFF0000u);
        }
    }
    __syncthreads();
    const int n = tid >> 4, jb = (tid & 15) * 32;
    const int gbase = (n >> 3) * 4096, n8 = n & 7;
#pragma unroll
    for (int it = 0; it < 8; it++) {
        int j = jb + it * 4;
        float4 v;
        v.x = sm[gbase + (j + 0) * 8 + n8];
        v.y = sm[gbase + (j + 1) * 8 + n8];
        v.z = sm[gbase + (j + 2) * 8 + n8];
        v.w = sm[gbase + (j + 3) * 8 + n8];
        *(float4*)(out + ((size_t)n * T_ + t) * H_ + j) = v;
    }
}

// ---------------- launch ----------------------------------------------------------
extern "C" void kernel_launch(void* const* d_in, const int* in_sizes, int n_in,
                              void* d_out, int out_size)
{
    const float* x    = (const float*)d_in[0];
    const float* h0   = (const float*)d_in[1];
    const float* Wx   = (const float*)d_in[2];
    const float* Wh   = (const float*)d_in[3];
    const float* bias = (const float*)d_in[4];
    float* out = (float*)d_out;

    init_state_kernel<<<64, 256>>>(h0);

    const int sh1 = (2 * AS_BUF + 2 * BS_BUF) * (int)sizeof(float);
    cudaFuncSetAttribute(gemm_xw_tc, cudaFuncAttributeMaxDynamicSharedMemorySize, sh1);
    dim3 g1(G4 / 128, (N_ * T_) / 128);
    gemm_xw_tc<<<g1, 256, sh1>>>(x, Wx, bias);

    dim3 gt1(T_, 4);
    xw_transpose_kernel<<<gt1, 512>>>();

    const int shmem = (32768 + 32768 + 4096 + 4096) * 2 + 16 * APW * 8;  // 184320 B
    cudaFuncSetAttribute(lstm_rec_kernel, cudaFuncAttributeMaxDynamicSharedMemorySize, shmem);
    lstm_rec_kernel<<<NB, NTH, shmem>>>(Wh);

    cudaFuncSetAttribute(out_transpose_kernel, cudaFuncAttributeMaxDynamicSharedMemorySize, 65536);
    out_transpose_kernel<<<T_, 512, 65536>>>(out);
}